// round 15
// baseline (speedup 1.0000x reference)
#include <cuda_runtime.h>
#include <cstdint>
#include <cstddef>

// Problem constants
#define N_TOT 131072   // B*S points
#define D_DIM 256      // feature dim
#define K_CL  512      // clusters

#define MT 128         // points per CTA tile (argmin)
#define TAU 0.2f       // tf32 near-tie threshold (6.5 sigma of 0.03 RMS)
#define MT2 64         // points per CTA tile (refine1)
#define TAU2 1e-3f     // split-tf32 threshold (err < 3e-5 -> >16x margin)
#define PPC 256        // points per gather CTA

// ---- argmin_mma crosswise SMEM layout ----
// X: addr(row, qc, ksl) = row*XRS + qc*XQS + ksl   (d = ksl*8 + qc, ksl 0..31)
//    XRS=304 (row step = 64B mod 128), XQS=36 (qc step = 16B mod 128)
// B chunk (128 clusters x 32 dims): addr(n, qc, ksl) = n*BRS + qc*BQS + ksl
//    BRS=48 (64B step), BQS=4 (16B step), ksl 0..3
#define XRS 304
#define XQS 36
#define BRS 48
#define BQS 4
#define SM_X   0                          // 128*304*4 = 155648
#define SM_B0  155648                     // 128*48*4  = 24576
#define SM_B1  180224
#define SM_C2  204800                     // 512 f32 = 2048
#define SM_BV  206848                     // float[4][128]
#define SM_SV  208896
#define SM_IV  210944
#define SMEM_TOTAL 212992

// ---- refine1 SMEM layout (unchanged, proven) ----
#define XSTR 260
#define BSTR2 36
#define R_XH  0
#define R_XL  66560
#define R_BH0 133120
#define R_BL0 151552
#define R_BH1 169984
#define R_BL1 188416
#define R_C2  206848
#define R_PL  208896
#define R_BV  209152
#define R_SV  210176
#define R_IV  211200
#define SMEM2_TOTAL 212224

// Scratch (device globals — no allocation allowed)
__device__ int   g_idx[N_TOT];
__device__ int   g_rank[N_TOT];
__device__ int   g_order[N_TOT];
__device__ float g_sums[K_CL * D_DIM];
__device__ int   g_counts[K_CL];
__device__ int   g_off[K_CL];
__device__ float g_c2[K_CL];
__device__ int   g_nref;
__device__ int   g_rlist[N_TOT];
__device__ int   g_nref2;
__device__ int   g_rlist2[N_TOT];

// ---------------- portable PTX helpers (NO 'a'-gated features) -------------
__device__ __forceinline__ uint32_t f2tf(float f) {
    uint32_t r;
    asm("cvt.rna.tf32.f32 %0, %1;" : "=r"(r) : "f"(f));
    return r;
}
__device__ __forceinline__ void mma8(float* d, const uint32_t* a, const uint32_t* b) {
    asm volatile(
        "mma.sync.aligned.m16n8k8.row.col.f32.tf32.tf32.f32 "
        "{%0,%1,%2,%3}, {%4,%5,%6,%7}, {%8,%9}, {%0,%1,%2,%3};"
        : "+f"(d[0]), "+f"(d[1]), "+f"(d[2]), "+f"(d[3])
        : "r"(a[0]), "r"(a[1]), "r"(a[2]), "r"(a[3]), "r"(b[0]), "r"(b[1]));
}
__device__ __forceinline__ float fcomp(const float4& v, int j) {
    return ((const float*)&v)[j];
}

// ---------------------------------------------------------------------------
// init: zero sums/counts/refine counters, c2[k] = sum_d C[k][d]^2 (fp64->fp32)
// ---------------------------------------------------------------------------
__global__ void init_kernel(const float* __restrict__ C) {
    int t = blockIdx.x * blockDim.x + threadIdx.x;
    if (t == 0) { g_nref = 0; g_nref2 = 0; }
    if (t < K_CL * D_DIM) g_sums[t] = 0.0f;
    if (t < K_CL) {
        g_counts[t] = 0;
        const float4* c = (const float4*)(C + (size_t)t * D_DIM);
        double s = 0.0;
        #pragma unroll
        for (int j = 0; j < D_DIM / 4; ++j) {
            float4 v = c[j];
            s += (double)v.x * v.x + (double)v.y * v.y
               + (double)v.z * v.z + (double)v.w * v.w;
        }
        g_c2[t] = (float)s;
    }
}

__global__ void pad_kernel() {}

// ---------------------------------------------------------------------------
// argmin_mma: 512 thr, 4m x 4n grid of 32x32 warp tiles, crosswise smem layout.
// Fragment values and MMA order identical to R14 -> scores bit-identical.
// Inner loop: 16 LDS.128 + 32 HMMA per q (vs 128 LDS.32 + 64 HMMA per 2q).
// ---------------------------------------------------------------------------
__global__ __launch_bounds__(512)
void argmin_mma(const float* __restrict__ X, const float* __restrict__ C,
                float* __restrict__ out) {
    extern __shared__ char smem[];
    const int tid  = threadIdx.x;
    const int wid  = tid >> 5, lane = tid & 31;
    const int qrow = lane >> 2, qcol = lane & 3;
    const int wm   = wid & 3,  wn   = wid >> 2;   // 4m x 4n warp grid
    const int RM   = wm * 32,  CN   = wn * 32;
    const int n0   = blockIdx.x * MT;

    float* Xs  = (float*)(smem + SM_X);
    float* Bb[2] = { (float*)(smem + SM_B0), (float*)(smem + SM_B1) };
    float* c2s = (float*)(smem + SM_C2);
    float* bvS = (float*)(smem + SM_BV);
    float* svS = (float*)(smem + SM_SV);
    int*   ivS = (int*)  (smem + SM_IV);

    c2s[tid] = g_c2[tid];

    // B chunk path: 128 clusters x 32 dims; LDG regs -> cvt -> crosswise STS
    float4 pr[2];
    auto ldgB = [&](int q) {
        const int kt = (q >> 3) * 128, db = (q & 7) * 32;
        #pragma unroll
        for (int i = 0; i < 2; ++i) {
            int idx = i * 512 + tid;
            int r = idx >> 3, fj = idx & 7;
            pr[i] = *(const float4*)(C + (size_t)(kt + r) * D_DIM + db + fj * 4);
        }
    };
    auto stsB = [&](float* B) {
        #pragma unroll
        for (int i = 0; i < 2; ++i) {
            int idx = i * 512 + tid;
            int r = idx >> 3, fj = idx & 7;
            int ksl = fj >> 1, qc0 = (fj & 1) * 4;
            float* p = B + r * BRS + qc0 * BQS + ksl;
            p[0 * BQS] = __uint_as_float(f2tf(pr[i].x));
            p[1 * BQS] = __uint_as_float(f2tf(pr[i].y));
            p[2 * BQS] = __uint_as_float(f2tf(pr[i].z));
            p[3 * BQS] = __uint_as_float(f2tf(pr[i].w));
        }
    };

    ldgB(0);
    // X tile -> crosswise tf32 smem (store through same address function)
    #pragma unroll
    for (int i = 0; i < 16; ++i) {
        int idx = i * 512 + tid;
        int r = idx >> 6, s = idx & 63;
        float4 v = *(const float4*)(X + (size_t)(n0 + r) * D_DIM + s * 4);
        int ksl = s >> 1, qc0 = (s & 1) * 4;
        float* p = Xs + r * XRS + qc0 * XQS + ksl;
        p[0 * XQS] = __uint_as_float(f2tf(v.x));
        p[1 * XQS] = __uint_as_float(f2tf(v.y));
        p[2 * XQS] = __uint_as_float(f2tf(v.z));
        p[3 * XQS] = __uint_as_float(f2tf(v.w));
    }
    stsB(Bb[0]);
    ldgB(1);
    __syncthreads();

    float acc[2][4][4];
    #pragma unroll
    for (int a = 0; a < 2; ++a)
        #pragma unroll
        for (int b = 0; b < 4; ++b)
            #pragma unroll
            for (int c = 0; c < 4; ++c) acc[a][b][c] = 0.0f;

    float best[4], sec[4];
    int   idx4[4];
    #pragma unroll
    for (int t = 0; t < 4; ++t) { best[t] = 3.4e38f; sec[t] = 3.4e38f; idx4[t] = 0; }

    // 32 chunks: kp = q>>3 (128-cluster pass), dc = q&7 (32-dim slice)
    for (int q = 0; q < 32; ++q) {
        const float* Bs = Bb[q & 1];
        const int dc = q & 7;

        // B fragments: 8 LDS.128 cover 4 ks-steps for all 4 nt
        float4 bf[4][2];
        #pragma unroll
        for (int nt = 0; nt < 4; ++nt) {
            int n = CN + nt * 8 + qrow;
            bf[nt][0] = *(const float4*)(Bs + n * BRS + qcol * BQS);
            bf[nt][1] = *(const float4*)(Bs + n * BRS + (qcol + 4) * BQS);
        }
        #pragma unroll
        for (int mt = 0; mt < 2; ++mt) {
            int r = RM + mt * 16 + qrow;
            float4 a0 = *(const float4*)(Xs + r * XRS + qcol * XQS + dc * 4);
            float4 a1 = *(const float4*)(Xs + (r + 8) * XRS + qcol * XQS + dc * 4);
            float4 a2 = *(const float4*)(Xs + r * XRS + (qcol + 4) * XQS + dc * 4);
            float4 a3 = *(const float4*)(Xs + (r + 8) * XRS + (qcol + 4) * XQS + dc * 4);
            #pragma unroll
            for (int ks = 0; ks < 4; ++ks) {
                uint32_t Af[4] = {
                    __float_as_uint(fcomp(a0, ks)), __float_as_uint(fcomp(a1, ks)),
                    __float_as_uint(fcomp(a2, ks)), __float_as_uint(fcomp(a3, ks)) };
                #pragma unroll
                for (int nt = 0; nt < 4; ++nt) {
                    uint32_t Bf[2] = {
                        __float_as_uint(fcomp(bf[nt][0], ks)),
                        __float_as_uint(fcomp(bf[nt][1], ks)) };
                    mma8(acc[mt][nt], Af, Bf);
                }
            }
        }

        if (dc == 7) {
            // pass epilogue: score = c2 - 2*dot, per-slot top-2, zero acc
            const int kt = (q >> 3) * 128;
            #pragma unroll
            for (int mt = 0; mt < 2; ++mt) {
                #pragma unroll
                for (int nt = 0; nt < 4; ++nt) {
                    int k0 = kt + CN + nt * 8 + 2 * qcol;
                    float c20 = c2s[k0], c21 = c2s[k0 + 1];
                    float s0 = fmaf(-2.0f, acc[mt][nt][0], c20);
                    float s1 = fmaf(-2.0f, acc[mt][nt][1], c21);
                    float s2 = fmaf(-2.0f, acc[mt][nt][2], c20);
                    float s3 = fmaf(-2.0f, acc[mt][nt][3], c21);
                    int t0 = mt * 2, t1 = mt * 2 + 1;
                    if (s0 < sec[t0]) { if (s0 < best[t0]) { sec[t0] = best[t0]; best[t0] = s0; idx4[t0] = k0; } else sec[t0] = s0; }
                    if (s1 < sec[t0]) { if (s1 < best[t0]) { sec[t0] = best[t0]; best[t0] = s1; idx4[t0] = k0 + 1; } else sec[t0] = s1; }
                    if (s2 < sec[t1]) { if (s2 < best[t1]) { sec[t1] = best[t1]; best[t1] = s2; idx4[t1] = k0; } else sec[t1] = s2; }
                    if (s3 < sec[t1]) { if (s3 < best[t1]) { sec[t1] = best[t1]; best[t1] = s3; idx4[t1] = k0 + 1; } else sec[t1] = s3; }
                    acc[mt][nt][0] = 0.0f; acc[mt][nt][1] = 0.0f;
                    acc[mt][nt][2] = 0.0f; acc[mt][nt][3] = 0.0f;
                }
            }
        }

        __syncthreads();
        if (q + 1 < 32) stsB(Bb[(q + 1) & 1]);
        if (q + 2 < 32) ldgB(q + 2);
        if (q + 1 < 32) __syncthreads();
    }

    // quad merge (lanes differing in qcol share rows)
    #pragma unroll
    for (int t = 0; t < 4; ++t) {
        float b = best[t], s = sec[t];
        int   i = idx4[t];
        #pragma unroll
        for (int o = 1; o <= 2; o <<= 1) {
            float b2 = __shfl_xor_sync(0xFFFFFFFFu, b, o);
            float s2 = __shfl_xor_sync(0xFFFFFFFFu, s, o);
            int   i2 = __shfl_xor_sync(0xFFFFFFFFu, i, o);
            if (b2 < b || (b2 == b && i2 < i)) { s = fminf(b, s2); b = b2; i = i2; }
            else                               { s = fminf(s, b2); }
        }
        if (qcol == 0) {
            int row = RM + (t >> 1) * 16 + qrow + (t & 1) * 8;
            bvS[wn * 128 + row] = b;
            svS[wn * 128 + row] = s;
            ivS[wn * 128 + row] = i;
        }
    }
    __syncthreads();

    // final cross-warp-column merge + decision (one thread per point)
    if (tid < 128) {
        float bb = bvS[tid], ss = svS[tid];
        int   ii = ivS[tid];
        #pragma unroll
        for (int w = 1; w < 4; ++w) {
            float b2 = bvS[w * 128 + tid], s2 = svS[w * 128 + tid];
            int   i2 = ivS[w * 128 + tid];
            if (b2 < bb || (b2 == bb && i2 < ii)) { ss = fminf(bb, s2); bb = b2; ii = i2; }
            else                                   { ss = fminf(ss, b2); }
        }
        int n = n0 + tid;
        g_idx[n] = ii;
        int mark = ii;
        if (ss - bb < TAU) {
            int slot = atomicAdd(&g_nref, 1);
            g_rlist[slot] = n;
            mark = -1;                      // tiered refine finalizes later
        } else {
            g_rank[n] = atomicAdd(&g_counts[ii], 1);   // fused rank
        }
        ivS[tid] = mark;
    }
    __syncthreads();

    // stream full one-hot rows (replaces global memset)
    #pragma unroll
    for (int i = 0; i < 32; ++i) {
        int idx = i * 512 + tid;
        int row = idx >> 7, s = idx & 127;
        int m = ivS[row];
        float4 v = make_float4(0.f, 0.f, 0.f, 0.f);
        if ((m >> 2) == s) ((float*)&v)[m & 3] = 1.0f;
        __stcs((float4*)(out + (size_t)(n0 + row) * K_CL + s * 4), v);
    }
}

// ---------------------------------------------------------------------------
// refine1: split-tf32 (3-pass) MMA re-score of near-tie points (79us measured)
// + fused rank for points it finalizes. (R14 verbatim)
// ---------------------------------------------------------------------------
__global__ __launch_bounds__(256)
void refine1_mma(const float* __restrict__ X, const float* __restrict__ C,
                 float* __restrict__ out) {
    const int nref  = g_nref;
    const int tile0 = blockIdx.x * MT2;
    if (tile0 >= nref) return;

    extern __shared__ char smem[];
    const int tid  = threadIdx.x;
    const int wid  = tid >> 5, lane = tid & 31;
    const int qrow = lane >> 2, qcol = lane & 3;
    const int wm   = wid & 1,  wn   = wid >> 1;
    const int RM   = wm * 32,  CN   = wn * 32;

    float* Xh  = (float*)(smem + R_XH);
    float* Xl  = (float*)(smem + R_XL);
    float* Bh[2] = { (float*)(smem + R_BH0), (float*)(smem + R_BH1) };
    float* Bl[2] = { (float*)(smem + R_BL0), (float*)(smem + R_BL1) };
    float* c2s = (float*)(smem + R_C2);
    int*   plist = (int*)(smem + R_PL);
    float* bvS = (float*)(smem + R_BV);
    float* svS = (float*)(smem + R_SV);
    int*   ivS = (int*)  (smem + R_IV);

    c2s[tid]       = g_c2[tid];
    c2s[tid + 256] = g_c2[tid + 256];
    if (tid < MT2) {
        int idx = tile0 + tid;
        plist[tid] = g_rlist[idx < nref ? idx : nref - 1];
    }
    __syncthreads();

    float4 pr[4];
    auto ldgB = [&](int q) {
        const int kt = (q >> 3) * 128, db = (q & 7) * 32;
        #pragma unroll
        for (int i = 0; i < 4; ++i) {
            int idx = i * 256 + tid;
            int r = idx >> 3, s = idx & 7;
            pr[i] = *(const float4*)(C + (size_t)(kt + r) * D_DIM + db + s * 4);
        }
    };
    auto stsB = [&](float* BH, float* BL) {
        #pragma unroll
        for (int i = 0; i < 4; ++i) {
            int idx = i * 256 + tid;
            int r = idx >> 3, s = idx & 7;
            float4 h, l;
            h.x = __uint_as_float(f2tf(pr[i].x)); l.x = __uint_as_float(f2tf(pr[i].x - h.x));
            h.y = __uint_as_float(f2tf(pr[i].y)); l.y = __uint_as_float(f2tf(pr[i].y - h.y));
            h.z = __uint_as_float(f2tf(pr[i].z)); l.z = __uint_as_float(f2tf(pr[i].z - h.z));
            h.w = __uint_as_float(f2tf(pr[i].w)); l.w = __uint_as_float(f2tf(pr[i].w - h.w));
            *(float4*)(BH + r * BSTR2 + s * 4) = h;
            *(float4*)(BL + r * BSTR2 + s * 4) = l;
        }
    };

    ldgB(0);
    #pragma unroll
    for (int i = 0; i < 16; ++i) {
        int idx = i * 256 + tid;
        int r = idx >> 6, s = idx & 63;
        float4 v = *(const float4*)(X + (size_t)plist[r] * D_DIM + s * 4);
        float4 h, l;
        h.x = __uint_as_float(f2tf(v.x)); l.x = __uint_as_float(f2tf(v.x - h.x));
        h.y = __uint_as_float(f2tf(v.y)); l.y = __uint_as_float(f2tf(v.y - h.y));
        h.z = __uint_as_float(f2tf(v.z)); l.z = __uint_as_float(f2tf(v.z - h.z));
        h.w = __uint_as_float(f2tf(v.w)); l.w = __uint_as_float(f2tf(v.w - h.w));
        *(float4*)(Xh + r * XSTR + s * 4) = h;
        *(float4*)(Xl + r * XSTR + s * 4) = l;
    }
    stsB(Bh[0], Bl[0]);
    ldgB(1);
    __syncthreads();

    float acc[2][4][4];
    #pragma unroll
    for (int a = 0; a < 2; ++a)
        #pragma unroll
        for (int b = 0; b < 4; ++b)
            #pragma unroll
            for (int c = 0; c < 4; ++c) acc[a][b][c] = 0.0f;

    float best[4], sec[4];
    int   idx4[4];
    #pragma unroll
    for (int t = 0; t < 4; ++t) { best[t] = 3.4e38f; sec[t] = 3.4e38f; idx4[t] = 0; }

    for (int q = 0; q < 32; ++q) {
        const int sbuf = q & 1;
        const int dc   = q & 7;
        const float* BsH = Bh[sbuf];
        const float* BsL = Bl[sbuf];

        #pragma unroll
        for (int ks = 0; ks < 4; ++ks) {
            const int dX = dc * 32 + ks * 8 + qcol;
            uint32_t Ah[2][4], Al[2][4];
            #pragma unroll
            for (int mt = 0; mt < 2; ++mt) {
                int r = RM + mt * 16 + qrow;
                Ah[mt][0] = __float_as_uint(Xh[r * XSTR + dX]);
                Ah[mt][1] = __float_as_uint(Xh[(r + 8) * XSTR + dX]);
                Ah[mt][2] = __float_as_uint(Xh[r * XSTR + dX + 4]);
                Ah[mt][3] = __float_as_uint(Xh[(r + 8) * XSTR + dX + 4]);
                Al[mt][0] = __float_as_uint(Xl[r * XSTR + dX]);
                Al[mt][1] = __float_as_uint(Xl[(r + 8) * XSTR + dX]);
                Al[mt][2] = __float_as_uint(Xl[r * XSTR + dX + 4]);
                Al[mt][3] = __float_as_uint(Xl[(r + 8) * XSTR + dX + 4]);
            }
            uint32_t BhF[4][2], BlF[4][2];
            #pragma unroll
            for (int nt = 0; nt < 4; ++nt) {
                int n = CN + nt * 8 + qrow;
                BhF[nt][0] = __float_as_uint(BsH[n * BSTR2 + ks * 8 + qcol]);
                BhF[nt][1] = __float_as_uint(BsH[n * BSTR2 + ks * 8 + 4 + qcol]);
                BlF[nt][0] = __float_as_uint(BsL[n * BSTR2 + ks * 8 + qcol]);
                BlF[nt][1] = __float_as_uint(BsL[n * BSTR2 + ks * 8 + 4 + qcol]);
            }
            #pragma unroll
            for (int mt = 0; mt < 2; ++mt)
                #pragma unroll
                for (int nt = 0; nt < 4; ++nt) {
                    mma8(acc[mt][nt], Ah[mt], BhF[nt]);
                    mma8(acc[mt][nt], Ah[mt], BlF[nt]);
                    mma8(acc[mt][nt], Al[mt], BhF[nt]);
                }
        }

        if (dc == 7) {
            const int kt = (q >> 3) * 128;
            #pragma unroll
            for (int mt = 0; mt < 2; ++mt) {
                #pragma unroll
                for (int nt = 0; nt < 4; ++nt) {
                    int k0 = kt + CN + nt * 8 + 2 * qcol;
                    float c20 = c2s[k0], c21 = c2s[k0 + 1];
                    float s0 = fmaf(-2.0f, acc[mt][nt][0], c20);
                    float s1 = fmaf(-2.0f, acc[mt][nt][1], c21);
                    float s2 = fmaf(-2.0f, acc[mt][nt][2], c20);
                    float s3 = fmaf(-2.0f, acc[mt][nt][3], c21);
                    int t0 = mt * 2, t1 = mt * 2 + 1;
                    if (s0 < sec[t0]) { if (s0 < best[t0]) { sec[t0] = best[t0]; best[t0] = s0; idx4[t0] = k0; } else sec[t0] = s0; }
                    if (s1 < sec[t0]) { if (s1 < best[t0]) { sec[t0] = best[t0]; best[t0] = s1; idx4[t0] = k0 + 1; } else sec[t0] = s1; }
                    if (s2 < sec[t1]) { if (s2 < best[t1]) { sec[t1] = best[t1]; best[t1] = s2; idx4[t1] = k0; } else sec[t1] = s2; }
                    if (s3 < sec[t1]) { if (s3 < best[t1]) { sec[t1] = best[t1]; best[t1] = s3; idx4[t1] = k0 + 1; } else sec[t1] = s3; }
                    acc[mt][nt][0] = 0.0f; acc[mt][nt][1] = 0.0f;
                    acc[mt][nt][2] = 0.0f; acc[mt][nt][3] = 0.0f;
                }
            }
        }

        __syncthreads();
        if (q + 1 < 32) stsB(Bh[(q + 1) & 1], Bl[(q + 1) & 1]);
        if (q + 2 < 32) ldgB(q + 2);
        if (q + 1 < 32) __syncthreads();
    }

    #pragma unroll
    for (int t = 0; t < 4; ++t) {
        float b = best[t], s = sec[t];
        int   i = idx4[t];
        #pragma unroll
        for (int o = 1; o <= 2; o <<= 1) {
            float b2 = __shfl_xor_sync(0xFFFFFFFFu, b, o);
            float s2 = __shfl_xor_sync(0xFFFFFFFFu, s, o);
            int   i2 = __shfl_xor_sync(0xFFFFFFFFu, i, o);
            if (b2 < b || (b2 == b && i2 < i)) { s = fminf(b, s2); b = b2; i = i2; }
            else                               { s = fminf(s, b2); }
        }
        if (qcol == 0) {
            int row = RM + (t >> 1) * 16 + qrow + (t & 1) * 8;
            bvS[wn * 64 + row] = b;
            svS[wn * 64 + row] = s;
            ivS[wn * 64 + row] = i;
        }
    }
    __syncthreads();

    if (tid < MT2) {
        float bb = bvS[tid], ss = svS[tid];
        int   ii = ivS[tid];
        #pragma unroll
        for (int w = 1; w < 4; ++w) {
            float b2 = bvS[w * 64 + tid], s2 = svS[w * 64 + tid];
            int   i2 = ivS[w * 64 + tid];
            if (b2 < bb || (b2 == bb && i2 < ii)) { ss = fminf(bb, s2); bb = b2; ii = i2; }
            else                                   { ss = fminf(ss, b2); }
        }
        int idx = tile0 + tid;
        if (idx < nref) {
            int n = plist[tid];
            if (ss - bb >= TAU2) {
                g_idx[n] = ii;
                out[(size_t)n * K_CL + ii] = 1.0f;   // row already all-zero
                g_rank[n] = atomicAdd(&g_counts[ii], 1);   // fused rank
            } else {
                int slot = atomicAdd(&g_nref2, 1);
                g_rlist2[slot] = n;                  // exact tier-2 decides
            }
        }
    }
}

// ---------------------------------------------------------------------------
// refine2 (exact tier): Kahan fp32 dots, reference rounding order + fused rank.
// ---------------------------------------------------------------------------
__device__ __forceinline__ void kadd(float& s, float& comp, float t) {
    float y = __fsub_rn(t, comp);
    float u = __fadd_rn(s, y);
    comp = __fsub_rn(__fsub_rn(u, s), y);
    s = u;
}

__global__ __launch_bounds__(256)
void refine2_kernel(const float* __restrict__ X, const float* __restrict__ C,
                    float* __restrict__ out) {
    __shared__ float  xsh[D_DIM];
    __shared__ double xwr[8];
    __shared__ float  x2sh;
    __shared__ float  rv[256];
    __shared__ int    ri[256];

    const int tid  = threadIdx.x;
    const int nref = g_nref2;

    for (int it = blockIdx.x; it < nref; it += gridDim.x) {
        const int n = g_rlist2[it];
        __syncthreads();
        xsh[tid] = X[(size_t)n * D_DIM + tid];
        __syncthreads();
        {
            double p = (double)xsh[tid] * (double)xsh[tid];
            #pragma unroll
            for (int o = 16; o >= 1; o >>= 1)
                p += __shfl_xor_sync(0xFFFFFFFFu, p, o);
            if ((tid & 31) == 0) xwr[tid >> 5] = p;
            __syncthreads();
            if (tid == 0) {
                double t = 0.0;
                #pragma unroll
                for (int w = 0; w < 8; ++w) t += xwr[w];
                x2sh = (float)t;
            }
            __syncthreads();
        }
        const float x2f = x2sh;
        const float4* xs4 = (const float4*)xsh;

        float bv = 3.4e38f;
        int   bi = 0x7fffffff;
        #pragma unroll
        for (int kk = 0; kk < 2; ++kk) {
            const int k = 2 * tid + kk;
            const float4* cp = (const float4*)(C + (size_t)k * D_DIM);
            float s = 0.0f, comp = 0.0f;
            #pragma unroll 4
            for (int j = 0; j < D_DIM / 4; ++j) {
                float4 cv = cp[j];
                float4 xv = xs4[j];
                kadd(s, comp, __fmul_rn(cv.x, xv.x));
                kadd(s, comp, __fmul_rn(cv.y, xv.y));
                kadd(s, comp, __fmul_rn(cv.z, xv.z));
                kadd(s, comp, __fmul_rn(cv.w, xv.w));
            }
            float dotf = __fadd_rn(s, comp);
            float m = __fmul_rn(2.0f, dotf);
            float a = __fsub_rn(x2f, m);
            float dist = __fadd_rn(a, g_c2[k]);
            if (dist < bv || (dist == bv && k < bi)) { bv = dist; bi = k; }
        }
        rv[tid] = bv; ri[tid] = bi;
        __syncthreads();
        #pragma unroll
        for (int st = 128; st > 0; st >>= 1) {
            if (tid < st) {
                float ov = rv[tid + st]; int oi = ri[tid + st];
                if (ov < rv[tid] || (ov == rv[tid] && oi < ri[tid])) {
                    rv[tid] = ov; ri[tid] = oi;
                }
            }
            __syncthreads();
        }
        if (tid == 0) {
            int kwin = ri[0];
            g_idx[n] = kwin;
            out[(size_t)n * K_CL + kwin] = 1.0f;
            g_rank[n] = atomicAdd(&g_counts[kwin], 1);   // fused rank
        }
    }
}

// ---------------------------------------------------------------------------
// sorted-gather accumulation: scan -> scatter -> gather (R14 verbatim)
// ---------------------------------------------------------------------------
__global__ void scan_kernel() {
    __shared__ int s[K_CL];
    int tid = threadIdx.x;
    s[tid] = g_counts[tid];
    __syncthreads();
    #pragma unroll
    for (int off = 1; off < K_CL; off <<= 1) {
        int v = (tid >= off) ? s[tid - off] : 0;
        __syncthreads();
        s[tid] += v;
        __syncthreads();
    }
    g_off[tid] = s[tid] - g_counts[tid];   // exclusive
}

__global__ void scatter_kernel() {
    int n = blockIdx.x * blockDim.x + threadIdx.x;
    if (n >= N_TOT) return;
    g_order[g_off[g_idx[n]] + g_rank[n]] = n;
}

__global__ __launch_bounds__(256)
void gather_kernel(const float* __restrict__ X) {
    __shared__ int ord[PPC];
    __shared__ int cls[PPC];
    const int tid = threadIdx.x;
    const int i0  = blockIdx.x * PPC;

    int n = g_order[i0 + tid];
    ord[tid] = n;
    cls[tid] = g_idx[n];
    __syncthreads();

    float a = 0.0f;
    int cur = cls[0];
    #pragma unroll 4
    for (int i = 0; i < PPC; ++i) {
        int c = cls[i];                    // uniform across threads
        if (c != cur) {
            atomicAdd(&g_sums[(size_t)cur * D_DIM + tid], a);
            a = 0.0f;
            cur = c;
        }
        a += X[(size_t)ord[i] * D_DIM + tid];
    }
    atomicAdd(&g_sums[(size_t)cur * D_DIM + tid], a);
}

// ---------------------------------------------------------------------------
__global__ void finalize_kernel(const float* __restrict__ C, float* __restrict__ outc) {
    int t = blockIdx.x * blockDim.x + threadIdx.x;
    if (t >= K_CL * D_DIM) return;
    int k = t >> 8;
    float cnt = (float)g_counts[k];
    float nc  = g_sums[t] / cnt;
    outc[t] = fmaf(0.9f, C[t], 0.1f * nc);
}

// ---------------------------------------------------------------------------
extern "C" void kernel_launch(void* const* d_in, const int* in_sizes, int n_in,
                              void* d_out, int out_size) {
    const float* X = (const float*)d_in[0];
    const float* C = (const float*)d_in[1];
    float* out = (float*)d_out;
    (void)in_sizes; (void)n_in; (void)out_size;

    cudaFuncSetAttribute(argmin_mma, cudaFuncAttributeMaxDynamicSharedMemorySize,
                         SMEM_TOTAL);
    cudaFuncSetAttribute(refine1_mma, cudaFuncAttributeMaxDynamicSharedMemorySize,
                         SMEM2_TOTAL);

    init_kernel<<<(K_CL * D_DIM + 255) / 256, 256>>>(C);
    pad_kernel<<<1, 32>>>();
    pad_kernel<<<1, 32>>>();
    argmin_mma<<<N_TOT / MT, 512, SMEM_TOTAL>>>(X, C, out);   // 4th -> ncu slot
    refine1_mma<<<N_TOT / MT2, 256, SMEM2_TOTAL>>>(X, C, out);
    refine2_kernel<<<512, 256>>>(X, C, out);
    scan_kernel<<<1, K_CL>>>();
    scatter_kernel<<<N_TOT / 256, 256>>>();
    gather_kernel<<<N_TOT / PPC, 256>>>(X);
    finalize_kernel<<<(K_CL * D_DIM + 255) / 256, 256>>>(C, out + (size_t)N_TOT * K_CL);
}

// round 16
// speedup vs baseline: 1.2522x; 1.2522x over previous
#include <cuda_runtime.h>
#include <cstdint>
#include <cstddef>

// Problem constants
#define N_TOT 131072   // B*S points
#define D_DIM 256      // feature dim
#define K_CL  512      // clusters

#define MT 128         // points per CTA tile (argmin)
#define TAU 0.2f       // tf32 near-tie threshold (6.5 sigma of 0.03 RMS)
#define MT2 64         // points per CTA tile (refine1)
#define TAU2 1e-3f     // split-tf32 threshold (err < 3e-5 -> >16x margin)
#define PPC 256        // points per gather CTA

// ---- dynamic SMEM layout for argmin_mma (bytes) — R14 proven ----
#define XSTR 260
#define BSTR 68
#define SM_X   0
#define SM_B0  133120
#define SM_B1  (SM_B0 + 34816)
#define SM_C2  (SM_B1 + 34816)
#define SM_BV  (SM_C2 + 2048)
#define SM_SV  (SM_BV + 2048)
#define SM_IV  (SM_SV + 2048)
#define SMEM_TOTAL (SM_IV + 2048)      // 210944

// ---- refine1 SMEM layout (proven) ----
#define BSTR2 36
#define R_XH  0
#define R_XL  66560
#define R_BH0 133120
#define R_BL0 151552
#define R_BH1 169984
#define R_BL1 188416
#define R_C2  206848
#define R_PL  208896
#define R_BV  209152
#define R_SV  210176
#define R_IV  211200
#define SMEM2_TOTAL 212224

// Scratch (device globals — no allocation allowed)
__device__ int   g_idx[N_TOT];
__device__ int   g_rank[N_TOT];
__device__ int   g_order[N_TOT];
__device__ float g_sums[K_CL * D_DIM];
__device__ int   g_counts[K_CL];
__device__ int   g_off[K_CL];
__device__ float g_c2[K_CL];
__device__ int   g_nref;
__device__ int   g_rlist[N_TOT];
__device__ int   g_nref2;
__device__ int   g_rlist2[N_TOT];

// ---------------- portable PTX helpers (NO 'a'-gated features) -------------
__device__ __forceinline__ uint32_t f2tf(float f) {
    uint32_t r;
    asm("cvt.rna.tf32.f32 %0, %1;" : "=r"(r) : "f"(f));
    return r;
}
__device__ __forceinline__ void mma8(float* d, const uint32_t* a, const uint32_t* b) {
    asm volatile(
        "mma.sync.aligned.m16n8k8.row.col.f32.tf32.tf32.f32 "
        "{%0,%1,%2,%3}, {%4,%5,%6,%7}, {%8,%9}, {%0,%1,%2,%3};"
        : "+f"(d[0]), "+f"(d[1]), "+f"(d[2]), "+f"(d[3])
        : "r"(a[0]), "r"(a[1]), "r"(a[2]), "r"(a[3]), "r"(b[0]), "r"(b[1]));
}

// ---------------------------------------------------------------------------
// init: zero sums/counts/refine counters, c2[k] = sum_d C[k][d]^2 (fp64->fp32)
// ---------------------------------------------------------------------------
__global__ void init_kernel(const float* __restrict__ C) {
    int t = blockIdx.x * blockDim.x + threadIdx.x;
    if (t == 0) { g_nref = 0; g_nref2 = 0; }
    if (t < K_CL * D_DIM) g_sums[t] = 0.0f;
    if (t < K_CL) {
        g_counts[t] = 0;
        const float4* c = (const float4*)(C + (size_t)t * D_DIM);
        double s = 0.0;
        #pragma unroll
        for (int j = 0; j < D_DIM / 4; ++j) {
            float4 v = c[j];
            s += (double)v.x * v.x + (double)v.y * v.y
               + (double)v.z * v.z + (double)v.w * v.w;
        }
        g_c2[t] = (float)s;
    }
}

// ---------------------------------------------------------------------------
// argmin_mma: R14 config verbatim (407.9us measured — mma.sync plateau).
// 512 thr, 4m x 4n grid of 32x32 warp tiles, fused rank for confident points.
// ---------------------------------------------------------------------------
__global__ __launch_bounds__(512)
void argmin_mma(const float* __restrict__ X, const float* __restrict__ C,
                float* __restrict__ out) {
    extern __shared__ char smem[];
    const int tid  = threadIdx.x;
    const int wid  = tid >> 5, lane = tid & 31;
    const int qrow = lane >> 2, qcol = lane & 3;
    const int wm   = wid & 3,  wn   = wid >> 2;   // 4m x 4n warp grid
    const int RM   = wm * 32,  CN   = wn * 32;
    const int n0   = blockIdx.x * MT;

    float* Xs  = (float*)(smem + SM_X);
    float* Bb[2] = { (float*)(smem + SM_B0), (float*)(smem + SM_B1) };
    float* c2s = (float*)(smem + SM_C2);
    float* bvS = (float*)(smem + SM_BV);
    float* svS = (float*)(smem + SM_SV);
    int*   ivS = (int*)  (smem + SM_IV);

    c2s[tid] = g_c2[tid];

    float4 pr[4];
    auto ldgB = [&](int q) {
        const int kt = (q >> 2) * 128, db = (q & 3) * 64;
        #pragma unroll
        for (int i = 0; i < 4; ++i) {
            int idx = i * 512 + tid;
            int r = idx >> 4, s = idx & 15;
            pr[i] = *(const float4*)(C + (size_t)(kt + r) * D_DIM + db + s * 4);
        }
    };
    auto stsB = [&](float* B) {
        #pragma unroll
        for (int i = 0; i < 4; ++i) {
            int idx = i * 512 + tid;
            int r = idx >> 4, s = idx & 15;
            float4 w;
            w.x = __uint_as_float(f2tf(pr[i].x));
            w.y = __uint_as_float(f2tf(pr[i].y));
            w.z = __uint_as_float(f2tf(pr[i].z));
            w.w = __uint_as_float(f2tf(pr[i].w));
            *(float4*)(B + r * BSTR + s * 4) = w;
        }
    };

    ldgB(0);
    #pragma unroll
    for (int i = 0; i < 16; ++i) {
        int idx = i * 512 + tid;
        int r = idx >> 6, s = idx & 63;
        float4 v = *(const float4*)(X + (size_t)(n0 + r) * D_DIM + s * 4);
        float4 w;
        w.x = __uint_as_float(f2tf(v.x));
        w.y = __uint_as_float(f2tf(v.y));
        w.z = __uint_as_float(f2tf(v.z));
        w.w = __uint_as_float(f2tf(v.w));
        *(float4*)(Xs + r * XSTR + s * 4) = w;
    }
    stsB(Bb[0]);
    ldgB(1);
    __syncthreads();

    float acc[2][4][4];
    #pragma unroll
    for (int a = 0; a < 2; ++a)
        #pragma unroll
        for (int b = 0; b < 4; ++b)
            #pragma unroll
            for (int c = 0; c < 4; ++c) acc[a][b][c] = 0.0f;

    float best[4], sec[4];
    int   idx4[4];
    #pragma unroll
    for (int t = 0; t < 4; ++t) { best[t] = 3.4e38f; sec[t] = 3.4e38f; idx4[t] = 0; }

    for (int q = 0; q < 16; ++q) {
        const float* Bs = Bb[q & 1];
        const int dbase = (q & 3) * 64;

        #pragma unroll
        for (int ks = 0; ks < 8; ++ks) {
            const int dX = dbase + ks * 8 + qcol;
            uint32_t Af[2][4];
            #pragma unroll
            for (int mt = 0; mt < 2; ++mt) {
                int r = RM + mt * 16 + qrow;
                Af[mt][0] = __float_as_uint(Xs[r * XSTR + dX]);
                Af[mt][1] = __float_as_uint(Xs[(r + 8) * XSTR + dX]);
                Af[mt][2] = __float_as_uint(Xs[r * XSTR + dX + 4]);
                Af[mt][3] = __float_as_uint(Xs[(r + 8) * XSTR + dX + 4]);
            }
            uint32_t Bf[4][2];
            #pragma unroll
            for (int nt = 0; nt < 4; ++nt) {
                int n = CN + nt * 8 + qrow;
                Bf[nt][0] = __float_as_uint(Bs[n * BSTR + ks * 8 + qcol]);
                Bf[nt][1] = __float_as_uint(Bs[n * BSTR + ks * 8 + 4 + qcol]);
            }
            #pragma unroll
            for (int mt = 0; mt < 2; ++mt)
                #pragma unroll
                for (int nt = 0; nt < 4; ++nt)
                    mma8(acc[mt][nt], Af[mt], Bf[nt]);
        }

        if ((q & 3) == 3) {
            const int kt = (q >> 2) * 128;
            #pragma unroll
            for (int mt = 0; mt < 2; ++mt) {
                #pragma unroll
                for (int nt = 0; nt < 4; ++nt) {
                    int k0 = kt + CN + nt * 8 + 2 * qcol;
                    float c20 = c2s[k0], c21 = c2s[k0 + 1];
                    float s0 = fmaf(-2.0f, acc[mt][nt][0], c20);
                    float s1 = fmaf(-2.0f, acc[mt][nt][1], c21);
                    float s2 = fmaf(-2.0f, acc[mt][nt][2], c20);
                    float s3 = fmaf(-2.0f, acc[mt][nt][3], c21);
                    int t0 = mt * 2, t1 = mt * 2 + 1;
                    if (s0 < sec[t0]) { if (s0 < best[t0]) { sec[t0] = best[t0]; best[t0] = s0; idx4[t0] = k0; } else sec[t0] = s0; }
                    if (s1 < sec[t0]) { if (s1 < best[t0]) { sec[t0] = best[t0]; best[t0] = s1; idx4[t0] = k0 + 1; } else sec[t0] = s1; }
                    if (s2 < sec[t1]) { if (s2 < best[t1]) { sec[t1] = best[t1]; best[t1] = s2; idx4[t1] = k0; } else sec[t1] = s2; }
                    if (s3 < sec[t1]) { if (s3 < best[t1]) { sec[t1] = best[t1]; best[t1] = s3; idx4[t1] = k0 + 1; } else sec[t1] = s3; }
                    acc[mt][nt][0] = 0.0f; acc[mt][nt][1] = 0.0f;
                    acc[mt][nt][2] = 0.0f; acc[mt][nt][3] = 0.0f;
                }
            }
        }

        __syncthreads();
        if (q + 1 < 16) stsB(Bb[(q + 1) & 1]);
        if (q + 2 < 16) ldgB(q + 2);
        if (q + 1 < 16) __syncthreads();
    }

    // quad merge (lanes differing in qcol share rows)
    #pragma unroll
    for (int t = 0; t < 4; ++t) {
        float b = best[t], s = sec[t];
        int   i = idx4[t];
        #pragma unroll
        for (int o = 1; o <= 2; o <<= 1) {
            float b2 = __shfl_xor_sync(0xFFFFFFFFu, b, o);
            float s2 = __shfl_xor_sync(0xFFFFFFFFu, s, o);
            int   i2 = __shfl_xor_sync(0xFFFFFFFFu, i, o);
            if (b2 < b || (b2 == b && i2 < i)) { s = fminf(b, s2); b = b2; i = i2; }
            else                               { s = fminf(s, b2); }
        }
        if (qcol == 0) {
            int row = RM + (t >> 1) * 16 + qrow + (t & 1) * 8;
            bvS[wn * 128 + row] = b;
            svS[wn * 128 + row] = s;
            ivS[wn * 128 + row] = i;
        }
    }
    __syncthreads();

    // final cross-warp-column merge + decision (one thread per point)
    if (tid < 128) {
        float bb = bvS[tid], ss = svS[tid];
        int   ii = ivS[tid];
        #pragma unroll
        for (int w = 1; w < 4; ++w) {
            float b2 = bvS[w * 128 + tid], s2 = svS[w * 128 + tid];
            int   i2 = ivS[w * 128 + tid];
            if (b2 < bb || (b2 == bb && i2 < ii)) { ss = fminf(bb, s2); bb = b2; ii = i2; }
            else                                   { ss = fminf(ss, b2); }
        }
        int n = n0 + tid;
        g_idx[n] = ii;
        int mark = ii;
        if (ss - bb < TAU) {
            int slot = atomicAdd(&g_nref, 1);
            g_rlist[slot] = n;
            mark = -1;                      // tiered refine finalizes later
        } else {
            g_rank[n] = atomicAdd(&g_counts[ii], 1);   // fused rank
        }
        ivS[tid] = mark;
    }
    __syncthreads();

    // stream full one-hot rows (replaces global memset)
    #pragma unroll
    for (int i = 0; i < 32; ++i) {
        int idx = i * 512 + tid;
        int row = idx >> 7, s = idx & 127;
        int m = ivS[row];
        float4 v = make_float4(0.f, 0.f, 0.f, 0.f);
        if ((m >> 2) == s) ((float*)&v)[m & 3] = 1.0f;
        __stcs((float4*)(out + (size_t)(n0 + row) * K_CL + s * 4), v);
    }
}

// ---------------------------------------------------------------------------
// refine1: split-tf32 (3-pass) MMA re-score of near-tie points (79us measured)
// + fused rank for points it finalizes.
// ---------------------------------------------------------------------------
__global__ __launch_bounds__(256)
void refine1_mma(const float* __restrict__ X, const float* __restrict__ C,
                 float* __restrict__ out) {
    const int nref  = g_nref;
    const int tile0 = blockIdx.x * MT2;
    if (tile0 >= nref) return;

    extern __shared__ char smem[];
    const int tid  = threadIdx.x;
    const int wid  = tid >> 5, lane = tid & 31;
    const int qrow = lane >> 2, qcol = lane & 3;
    const int wm   = wid & 1,  wn   = wid >> 1;
    const int RM   = wm * 32,  CN   = wn * 32;

    float* Xh  = (float*)(smem + R_XH);
    float* Xl  = (float*)(smem + R_XL);
    float* Bh[2] = { (float*)(smem + R_BH0), (float*)(smem + R_BH1) };
    float* Bl[2] = { (float*)(smem + R_BL0), (float*)(smem + R_BL1) };
    float* c2s = (float*)(smem + R_C2);
    int*   plist = (int*)(smem + R_PL);
    float* bvS = (float*)(smem + R_BV);
    float* svS = (float*)(smem + R_SV);
    int*   ivS = (int*)  (smem + R_IV);

    c2s[tid]       = g_c2[tid];
    c2s[tid + 256] = g_c2[tid + 256];
    if (tid < MT2) {
        int idx = tile0 + tid;
        plist[tid] = g_rlist[idx < nref ? idx : nref - 1];
    }
    __syncthreads();

    float4 pr[4];
    auto ldgB = [&](int q) {
        const int kt = (q >> 3) * 128, db = (q & 7) * 32;
        #pragma unroll
        for (int i = 0; i < 4; ++i) {
            int idx = i * 256 + tid;
            int r = idx >> 3, s = idx & 7;
            pr[i] = *(const float4*)(C + (size_t)(kt + r) * D_DIM + db + s * 4);
        }
    };
    auto stsB = [&](float* BH, float* BL) {
        #pragma unroll
        for (int i = 0; i < 4; ++i) {
            int idx = i * 256 + tid;
            int r = idx >> 3, s = idx & 7;
            float4 h, l;
            h.x = __uint_as_float(f2tf(pr[i].x)); l.x = __uint_as_float(f2tf(pr[i].x - h.x));
            h.y = __uint_as_float(f2tf(pr[i].y)); l.y = __uint_as_float(f2tf(pr[i].y - h.y));
            h.z = __uint_as_float(f2tf(pr[i].z)); l.z = __uint_as_float(f2tf(pr[i].z - h.z));
            h.w = __uint_as_float(f2tf(pr[i].w)); l.w = __uint_as_float(f2tf(pr[i].w - h.w));
            *(float4*)(BH + r * BSTR2 + s * 4) = h;
            *(float4*)(BL + r * BSTR2 + s * 4) = l;
        }
    };

    ldgB(0);
    #pragma unroll
    for (int i = 0; i < 16; ++i) {
        int idx = i * 256 + tid;
        int r = idx >> 6, s = idx & 63;
        float4 v = *(const float4*)(X + (size_t)plist[r] * D_DIM + s * 4);
        float4 h, l;
        h.x = __uint_as_float(f2tf(v.x)); l.x = __uint_as_float(f2tf(v.x - h.x));
        h.y = __uint_as_float(f2tf(v.y)); l.y = __uint_as_float(f2tf(v.y - h.y));
        h.z = __uint_as_float(f2tf(v.z)); l.z = __uint_as_float(f2tf(v.z - h.z));
        h.w = __uint_as_float(f2tf(v.w)); l.w = __uint_as_float(f2tf(v.w - h.w));
        *(float4*)(Xh + r * 260 + s * 4) = h;
        *(float4*)(Xl + r * 260 + s * 4) = l;
    }
    stsB(Bh[0], Bl[0]);
    ldgB(1);
    __syncthreads();

    float acc[2][4][4];
    #pragma unroll
    for (int a = 0; a < 2; ++a)
        #pragma unroll
        for (int b = 0; b < 4; ++b)
            #pragma unroll
            for (int c = 0; c < 4; ++c) acc[a][b][c] = 0.0f;

    float best[4], sec[4];
    int   idx4[4];
    #pragma unroll
    for (int t = 0; t < 4; ++t) { best[t] = 3.4e38f; sec[t] = 3.4e38f; idx4[t] = 0; }

    for (int q = 0; q < 32; ++q) {
        const int sbuf = q & 1;
        const int dc   = q & 7;
        const float* BsH = Bh[sbuf];
        const float* BsL = Bl[sbuf];

        #pragma unroll
        for (int ks = 0; ks < 4; ++ks) {
            const int dX = dc * 32 + ks * 8 + qcol;
            uint32_t Ah[2][4], Al[2][4];
            #pragma unroll
            for (int mt = 0; mt < 2; ++mt) {
                int r = RM + mt * 16 + qrow;
                Ah[mt][0] = __float_as_uint(Xh[r * 260 + dX]);
                Ah[mt][1] = __float_as_uint(Xh[(r + 8) * 260 + dX]);
                Ah[mt][2] = __float_as_uint(Xh[r * 260 + dX + 4]);
                Ah[mt][3] = __float_as_uint(Xh[(r + 8) * 260 + dX + 4]);
                Al[mt][0] = __float_as_uint(Xl[r * 260 + dX]);
                Al[mt][1] = __float_as_uint(Xl[(r + 8) * 260 + dX]);
                Al[mt][2] = __float_as_uint(Xl[r * 260 + dX + 4]);
                Al[mt][3] = __float_as_uint(Xl[(r + 8) * 260 + dX + 4]);
            }
            uint32_t BhF[4][2], BlF[4][2];
            #pragma unroll
            for (int nt = 0; nt < 4; ++nt) {
                int n = CN + nt * 8 + qrow;
                BhF[nt][0] = __float_as_uint(BsH[n * BSTR2 + ks * 8 + qcol]);
                BhF[nt][1] = __float_as_uint(BsH[n * BSTR2 + ks * 8 + 4 + qcol]);
                BlF[nt][0] = __float_as_uint(BsL[n * BSTR2 + ks * 8 + qcol]);
                BlF[nt][1] = __float_as_uint(BsL[n * BSTR2 + ks * 8 + 4 + qcol]);
            }
            #pragma unroll
            for (int mt = 0; mt < 2; ++mt)
                #pragma unroll
                for (int nt = 0; nt < 4; ++nt) {
                    mma8(acc[mt][nt], Ah[mt], BhF[nt]);
                    mma8(acc[mt][nt], Ah[mt], BlF[nt]);
                    mma8(acc[mt][nt], Al[mt], BhF[nt]);
                }
        }

        if (dc == 7) {
            const int kt = (q >> 3) * 128;
            #pragma unroll
            for (int mt = 0; mt < 2; ++mt) {
                #pragma unroll
                for (int nt = 0; nt < 4; ++nt) {
                    int k0 = kt + CN + nt * 8 + 2 * qcol;
                    float c20 = c2s[k0], c21 = c2s[k0 + 1];
                    float s0 = fmaf(-2.0f, acc[mt][nt][0], c20);
                    float s1 = fmaf(-2.0f, acc[mt][nt][1], c21);
                    float s2 = fmaf(-2.0f, acc[mt][nt][2], c20);
                    float s3 = fmaf(-2.0f, acc[mt][nt][3], c21);
                    int t0 = mt * 2, t1 = mt * 2 + 1;
                    if (s0 < sec[t0]) { if (s0 < best[t0]) { sec[t0] = best[t0]; best[t0] = s0; idx4[t0] = k0; } else sec[t0] = s0; }
                    if (s1 < sec[t0]) { if (s1 < best[t0]) { sec[t0] = best[t0]; best[t0] = s1; idx4[t0] = k0 + 1; } else sec[t0] = s1; }
                    if (s2 < sec[t1]) { if (s2 < best[t1]) { sec[t1] = best[t1]; best[t1] = s2; idx4[t1] = k0; } else sec[t1] = s2; }
                    if (s3 < sec[t1]) { if (s3 < best[t1]) { sec[t1] = best[t1]; best[t1] = s3; idx4[t1] = k0 + 1; } else sec[t1] = s3; }
                    acc[mt][nt][0] = 0.0f; acc[mt][nt][1] = 0.0f;
                    acc[mt][nt][2] = 0.0f; acc[mt][nt][3] = 0.0f;
                }
            }
        }

        __syncthreads();
        if (q + 1 < 32) stsB(Bh[(q + 1) & 1], Bl[(q + 1) & 1]);
        if (q + 2 < 32) ldgB(q + 2);
        if (q + 1 < 32) __syncthreads();
    }

    #pragma unroll
    for (int t = 0; t < 4; ++t) {
        float b = best[t], s = sec[t];
        int   i = idx4[t];
        #pragma unroll
        for (int o = 1; o <= 2; o <<= 1) {
            float b2 = __shfl_xor_sync(0xFFFFFFFFu, b, o);
            float s2 = __shfl_xor_sync(0xFFFFFFFFu, s, o);
            int   i2 = __shfl_xor_sync(0xFFFFFFFFu, i, o);
            if (b2 < b || (b2 == b && i2 < i)) { s = fminf(b, s2); b = b2; i = i2; }
            else                               { s = fminf(s, b2); }
        }
        if (qcol == 0) {
            int row = RM + (t >> 1) * 16 + qrow + (t & 1) * 8;
            bvS[wn * 64 + row] = b;
            svS[wn * 64 + row] = s;
            ivS[wn * 64 + row] = i;
        }
    }
    __syncthreads();

    if (tid < MT2) {
        float bb = bvS[tid], ss = svS[tid];
        int   ii = ivS[tid];
        #pragma unroll
        for (int w = 1; w < 4; ++w) {
            float b2 = bvS[w * 64 + tid], s2 = svS[w * 64 + tid];
            int   i2 = ivS[w * 64 + tid];
            if (b2 < bb || (b2 == bb && i2 < ii)) { ss = fminf(bb, s2); bb = b2; ii = i2; }
            else                                   { ss = fminf(ss, b2); }
        }
        int idx = tile0 + tid;
        if (idx < nref) {
            int n = plist[tid];
            if (ss - bb >= TAU2) {
                g_idx[n] = ii;
                out[(size_t)n * K_CL + ii] = 1.0f;   // row already all-zero
                g_rank[n] = atomicAdd(&g_counts[ii], 1);   // fused rank
            } else {
                int slot = atomicAdd(&g_nref2, 1);
                g_rlist2[slot] = n;                  // exact tier-2 decides
            }
        }
    }
}

// ---------------------------------------------------------------------------
// refine2 (exact tier): Kahan fp32 dots, reference rounding order + fused rank.
// ---------------------------------------------------------------------------
__device__ __forceinline__ void kadd(float& s, float& comp, float t) {
    float y = __fsub_rn(t, comp);
    float u = __fadd_rn(s, y);
    comp = __fsub_rn(__fsub_rn(u, s), y);
    s = u;
}

__global__ __launch_bounds__(256)
void refine2_kernel(const float* __restrict__ X, const float* __restrict__ C,
                    float* __restrict__ out) {
    __shared__ float  xsh[D_DIM];
    __shared__ double xwr[8];
    __shared__ float  x2sh;
    __shared__ float  rv[256];
    __shared__ int    ri[256];

    const int tid  = threadIdx.x;
    const int nref = g_nref2;

    for (int it = blockIdx.x; it < nref; it += gridDim.x) {
        const int n = g_rlist2[it];
        __syncthreads();
        xsh[tid] = X[(size_t)n * D_DIM + tid];
        __syncthreads();
        {
            double p = (double)xsh[tid] * (double)xsh[tid];
            #pragma unroll
            for (int o = 16; o >= 1; o >>= 1)
                p += __shfl_xor_sync(0xFFFFFFFFu, p, o);
            if ((tid & 31) == 0) xwr[tid >> 5] = p;
            __syncthreads();
            if (tid == 0) {
                double t = 0.0;
                #pragma unroll
                for (int w = 0; w < 8; ++w) t += xwr[w];
                x2sh = (float)t;
            }
            __syncthreads();
        }
        const float x2f = x2sh;
        const float4* xs4 = (const float4*)xsh;

        float bv = 3.4e38f;
        int   bi = 0x7fffffff;
        #pragma unroll
        for (int kk = 0; kk < 2; ++kk) {
            const int k = 2 * tid + kk;
            const float4* cp = (const float4*)(C + (size_t)k * D_DIM);
            float s = 0.0f, comp = 0.0f;
            #pragma unroll 4
            for (int j = 0; j < D_DIM / 4; ++j) {
                float4 cv = cp[j];
                float4 xv = xs4[j];
                kadd(s, comp, __fmul_rn(cv.x, xv.x));
                kadd(s, comp, __fmul_rn(cv.y, xv.y));
                kadd(s, comp, __fmul_rn(cv.z, xv.z));
                kadd(s, comp, __fmul_rn(cv.w, xv.w));
            }
            float dotf = __fadd_rn(s, comp);
            float m = __fmul_rn(2.0f, dotf);
            float a = __fsub_rn(x2f, m);
            float dist = __fadd_rn(a, g_c2[k]);
            if (dist < bv || (dist == bv && k < bi)) { bv = dist; bi = k; }
        }
        rv[tid] = bv; ri[tid] = bi;
        __syncthreads();
        #pragma unroll
        for (int st = 128; st > 0; st >>= 1) {
            if (tid < st) {
                float ov = rv[tid + st]; int oi = ri[tid + st];
                if (ov < rv[tid] || (ov == rv[tid] && oi < ri[tid])) {
                    rv[tid] = ov; ri[tid] = oi;
                }
            }
            __syncthreads();
        }
        if (tid == 0) {
            int kwin = ri[0];
            g_idx[n] = kwin;
            out[(size_t)n * K_CL + kwin] = 1.0f;
            g_rank[n] = atomicAdd(&g_counts[kwin], 1);   // fused rank
        }
    }
}

// ---------------------------------------------------------------------------
// sorted-gather accumulation: scan -> scatter -> gather
// ---------------------------------------------------------------------------
__global__ void scan_kernel() {
    __shared__ int s[K_CL];
    int tid = threadIdx.x;
    s[tid] = g_counts[tid];
    __syncthreads();
    #pragma unroll
    for (int off = 1; off < K_CL; off <<= 1) {
        int v = (tid >= off) ? s[tid - off] : 0;
        __syncthreads();
        s[tid] += v;
        __syncthreads();
    }
    g_off[tid] = s[tid] - g_counts[tid];   // exclusive
}

__global__ void scatter_kernel() {
    int n = blockIdx.x * blockDim.x + threadIdx.x;
    if (n >= N_TOT) return;
    g_order[g_off[g_idx[n]] + g_rank[n]] = n;
}

__global__ __launch_bounds__(256)
void gather_kernel(const float* __restrict__ X) {
    __shared__ int ord[PPC];
    __shared__ int cls[PPC];
    const int tid = threadIdx.x;
    const int i0  = blockIdx.x * PPC;

    int n = g_order[i0 + tid];
    ord[tid] = n;
    cls[tid] = g_idx[n];
    __syncthreads();

    float a = 0.0f;
    int cur = cls[0];
    #pragma unroll 4
    for (int i = 0; i < PPC; ++i) {
        int c = cls[i];                    // uniform across threads
        if (c != cur) {
            atomicAdd(&g_sums[(size_t)cur * D_DIM + tid], a);
            a = 0.0f;
            cur = c;
        }
        a += X[(size_t)ord[i] * D_DIM + tid];
    }
    atomicAdd(&g_sums[(size_t)cur * D_DIM + tid], a);
}

// ---------------------------------------------------------------------------
__global__ void finalize_kernel(const float* __restrict__ C, float* __restrict__ outc) {
    int t = blockIdx.x * blockDim.x + threadIdx.x;
    if (t >= K_CL * D_DIM) return;
    int k = t >> 8;
    float cnt = (float)g_counts[k];
    float nc  = g_sums[t] / cnt;
    outc[t] = fmaf(0.9f, C[t], 0.1f * nc);
}

// ---------------------------------------------------------------------------
extern "C" void kernel_launch(void* const* d_in, const int* in_sizes, int n_in,
                              void* d_out, int out_size) {
    const float* X = (const float*)d_in[0];
    const float* C = (const float*)d_in[1];
    float* out = (float*)d_out;
    (void)in_sizes; (void)n_in; (void)out_size;

    cudaFuncSetAttribute(argmin_mma, cudaFuncAttributeMaxDynamicSharedMemorySize,
                         SMEM_TOTAL);
    cudaFuncSetAttribute(refine1_mma, cudaFuncAttributeMaxDynamicSharedMemorySize,
                         SMEM2_TOTAL);

    init_kernel<<<(K_CL * D_DIM + 255) / 256, 256>>>(C);
    argmin_mma<<<N_TOT / MT, 512, SMEM_TOTAL>>>(X, C, out);
    refine1_mma<<<N_TOT / MT2, 256, SMEM2_TOTAL>>>(X, C, out);
    refine2_kernel<<<512, 256>>>(X, C, out);
    scan_kernel<<<1, K_CL>>>();
    scatter_kernel<<<N_TOT / 256, 256>>>();
    gather_kernel<<<N_TOT / PPC, 256>>>(X);
    finalize_kernel<<<(K_CL * D_DIM + 255) / 256, 256>>>(C, out + (size_t)N_TOT * K_CL);
}

// round 17
// speedup vs baseline: 1.3183x; 1.0528x over previous
#include <cuda_runtime.h>
#include <cstdint>
#include <cstddef>

// Problem constants
#define N_TOT 131072   // B*S points
#define D_DIM 256      // feature dim
#define K_CL  512      // clusters

#define MT 128         // points per CTA tile (argmin)
#define TAU 0.2f       // tf32 near-tie threshold (6.5 sigma of 0.03 RMS)
#define MT2 64         // points per CTA tile (refine1)
#define TAU2 1e-3f     // split-tf32 threshold (err < 3e-5 -> >16x margin)
#define PPC 128        // points per gather CTA (halved serial depth, 1024 CTAs)

// ---- dynamic SMEM layout for argmin_mma (bytes) — R14/R16 proven ----
#define XSTR 260
#define BSTR 68
#define SM_X   0
#define SM_B0  133120
#define SM_B1  (SM_B0 + 34816)
#define SM_C2  (SM_B1 + 34816)
#define SM_BV  (SM_C2 + 2048)
#define SM_SV  (SM_BV + 2048)
#define SM_IV  (SM_SV + 2048)
#define SMEM_TOTAL (SM_IV + 2048)      // 210944

// ---- refine1 SMEM layout (proven) ----
#define BSTR2 36
#define R_XH  0
#define R_XL  66560
#define R_BH0 133120
#define R_BL0 151552
#define R_BH1 169984
#define R_BL1 188416
#define R_C2  206848
#define R_PL  208896
#define R_BV  209152
#define R_SV  210176
#define R_IV  211200
#define SMEM2_TOTAL 212224

// Scratch (device globals — no allocation allowed)
__device__ int   g_idx[N_TOT];
__device__ int   g_rank[N_TOT];
__device__ int   g_order[N_TOT];
__device__ float g_sums[K_CL * D_DIM];
__device__ int   g_counts[K_CL];
__device__ int   g_off[K_CL];
__device__ float g_c2[K_CL];
__device__ int   g_nref;
__device__ int   g_rlist[N_TOT];
__device__ int   g_nref2;
__device__ int   g_rlist2[N_TOT];

// ---------------- portable PTX helpers (NO 'a'-gated features) -------------
__device__ __forceinline__ uint32_t f2tf(float f) {
    uint32_t r;
    asm("cvt.rna.tf32.f32 %0, %1;" : "=r"(r) : "f"(f));
    return r;
}
__device__ __forceinline__ void mma8(float* d, const uint32_t* a, const uint32_t* b) {
    asm volatile(
        "mma.sync.aligned.m16n8k8.row.col.f32.tf32.tf32.f32 "
        "{%0,%1,%2,%3}, {%4,%5,%6,%7}, {%8,%9}, {%0,%1,%2,%3};"
        : "+f"(d[0]), "+f"(d[1]), "+f"(d[2]), "+f"(d[3])
        : "r"(a[0]), "r"(a[1]), "r"(a[2]), "r"(a[3]), "r"(b[0]), "r"(b[1]));
}

// ---------------------------------------------------------------------------
// init: zero sums/counts/refine counters, c2[k] = sum_d C[k][d]^2 (fp64->fp32)
// ---------------------------------------------------------------------------
__global__ void init_kernel(const float* __restrict__ C) {
    int t = blockIdx.x * blockDim.x + threadIdx.x;
    if (t == 0) { g_nref = 0; g_nref2 = 0; }
    if (t < K_CL * D_DIM) g_sums[t] = 0.0f;
    if (t < K_CL) {
        g_counts[t] = 0;
        const float4* c = (const float4*)(C + (size_t)t * D_DIM);
        double s = 0.0;
        #pragma unroll
        for (int j = 0; j < D_DIM / 4; ++j) {
            float4 v = c[j];
            s += (double)v.x * v.x + (double)v.y * v.y
               + (double)v.z * v.z + (double)v.w * v.w;
        }
        g_c2[t] = (float)s;
    }
}

// ---------------------------------------------------------------------------
// argmin_mma: measured-best config (407.9us — mma.sync plateau).
// 512 thr, 4m x 4n grid of 32x32 warp tiles, fused rank for confident points.
// ---------------------------------------------------------------------------
__global__ __launch_bounds__(512)
void argmin_mma(const float* __restrict__ X, const float* __restrict__ C,
                float* __restrict__ out) {
    extern __shared__ char smem[];
    const int tid  = threadIdx.x;
    const int wid  = tid >> 5, lane = tid & 31;
    const int qrow = lane >> 2, qcol = lane & 3;
    const int wm   = wid & 3,  wn   = wid >> 2;   // 4m x 4n warp grid
    const int RM   = wm * 32,  CN   = wn * 32;
    const int n0   = blockIdx.x * MT;

    float* Xs  = (float*)(smem + SM_X);
    float* Bb[2] = { (float*)(smem + SM_B0), (float*)(smem + SM_B1) };
    float* c2s = (float*)(smem + SM_C2);
    float* bvS = (float*)(smem + SM_BV);
    float* svS = (float*)(smem + SM_SV);
    int*   ivS = (int*)  (smem + SM_IV);

    c2s[tid] = g_c2[tid];

    float4 pr[4];
    auto ldgB = [&](int q) {
        const int kt = (q >> 2) * 128, db = (q & 3) * 64;
        #pragma unroll
        for (int i = 0; i < 4; ++i) {
            int idx = i * 512 + tid;
            int r = idx >> 4, s = idx & 15;
            pr[i] = *(const float4*)(C + (size_t)(kt + r) * D_DIM + db + s * 4);
        }
    };
    auto stsB = [&](float* B) {
        #pragma unroll
        for (int i = 0; i < 4; ++i) {
            int idx = i * 512 + tid;
            int r = idx >> 4, s = idx & 15;
            float4 w;
            w.x = __uint_as_float(f2tf(pr[i].x));
            w.y = __uint_as_float(f2tf(pr[i].y));
            w.z = __uint_as_float(f2tf(pr[i].z));
            w.w = __uint_as_float(f2tf(pr[i].w));
            *(float4*)(B + r * BSTR + s * 4) = w;
        }
    };

    ldgB(0);
    #pragma unroll
    for (int i = 0; i < 16; ++i) {
        int idx = i * 512 + tid;
        int r = idx >> 6, s = idx & 63;
        float4 v = *(const float4*)(X + (size_t)(n0 + r) * D_DIM + s * 4);
        float4 w;
        w.x = __uint_as_float(f2tf(v.x));
        w.y = __uint_as_float(f2tf(v.y));
        w.z = __uint_as_float(f2tf(v.z));
        w.w = __uint_as_float(f2tf(v.w));
        *(float4*)(Xs + r * XSTR + s * 4) = w;
    }
    stsB(Bb[0]);
    ldgB(1);
    __syncthreads();

    float acc[2][4][4];
    #pragma unroll
    for (int a = 0; a < 2; ++a)
        #pragma unroll
        for (int b = 0; b < 4; ++b)
            #pragma unroll
            for (int c = 0; c < 4; ++c) acc[a][b][c] = 0.0f;

    float best[4], sec[4];
    int   idx4[4];
    #pragma unroll
    for (int t = 0; t < 4; ++t) { best[t] = 3.4e38f; sec[t] = 3.4e38f; idx4[t] = 0; }

    for (int q = 0; q < 16; ++q) {
        const float* Bs = Bb[q & 1];
        const int dbase = (q & 3) * 64;

        #pragma unroll
        for (int ks = 0; ks < 8; ++ks) {
            const int dX = dbase + ks * 8 + qcol;
            uint32_t Af[2][4];
            #pragma unroll
            for (int mt = 0; mt < 2; ++mt) {
                int r = RM + mt * 16 + qrow;
                Af[mt][0] = __float_as_uint(Xs[r * XSTR + dX]);
                Af[mt][1] = __float_as_uint(Xs[(r + 8) * XSTR + dX]);
                Af[mt][2] = __float_as_uint(Xs[r * XSTR + dX + 4]);
                Af[mt][3] = __float_as_uint(Xs[(r + 8) * XSTR + dX + 4]);
            }
            uint32_t Bf[4][2];
            #pragma unroll
            for (int nt = 0; nt < 4; ++nt) {
                int n = CN + nt * 8 + qrow;
                Bf[nt][0] = __float_as_uint(Bs[n * BSTR + ks * 8 + qcol]);
                Bf[nt][1] = __float_as_uint(Bs[n * BSTR + ks * 8 + 4 + qcol]);
            }
            #pragma unroll
            for (int mt = 0; mt < 2; ++mt)
                #pragma unroll
                for (int nt = 0; nt < 4; ++nt)
                    mma8(acc[mt][nt], Af[mt], Bf[nt]);
        }

        if ((q & 3) == 3) {
            const int kt = (q >> 2) * 128;
            #pragma unroll
            for (int mt = 0; mt < 2; ++mt) {
                #pragma unroll
                for (int nt = 0; nt < 4; ++nt) {
                    int k0 = kt + CN + nt * 8 + 2 * qcol;
                    float c20 = c2s[k0], c21 = c2s[k0 + 1];
                    float s0 = fmaf(-2.0f, acc[mt][nt][0], c20);
                    float s1 = fmaf(-2.0f, acc[mt][nt][1], c21);
                    float s2 = fmaf(-2.0f, acc[mt][nt][2], c20);
                    float s3 = fmaf(-2.0f, acc[mt][nt][3], c21);
                    int t0 = mt * 2, t1 = mt * 2 + 1;
                    if (s0 < sec[t0]) { if (s0 < best[t0]) { sec[t0] = best[t0]; best[t0] = s0; idx4[t0] = k0; } else sec[t0] = s0; }
                    if (s1 < sec[t0]) { if (s1 < best[t0]) { sec[t0] = best[t0]; best[t0] = s1; idx4[t0] = k0 + 1; } else sec[t0] = s1; }
                    if (s2 < sec[t1]) { if (s2 < best[t1]) { sec[t1] = best[t1]; best[t1] = s2; idx4[t1] = k0; } else sec[t1] = s2; }
                    if (s3 < sec[t1]) { if (s3 < best[t1]) { sec[t1] = best[t1]; best[t1] = s3; idx4[t1] = k0 + 1; } else sec[t1] = s3; }
                    acc[mt][nt][0] = 0.0f; acc[mt][nt][1] = 0.0f;
                    acc[mt][nt][2] = 0.0f; acc[mt][nt][3] = 0.0f;
                }
            }
        }

        __syncthreads();
        if (q + 1 < 16) stsB(Bb[(q + 1) & 1]);
        if (q + 2 < 16) ldgB(q + 2);
        if (q + 1 < 16) __syncthreads();
    }

    // quad merge (lanes differing in qcol share rows)
    #pragma unroll
    for (int t = 0; t < 4; ++t) {
        float b = best[t], s = sec[t];
        int   i = idx4[t];
        #pragma unroll
        for (int o = 1; o <= 2; o <<= 1) {
            float b2 = __shfl_xor_sync(0xFFFFFFFFu, b, o);
            float s2 = __shfl_xor_sync(0xFFFFFFFFu, s, o);
            int   i2 = __shfl_xor_sync(0xFFFFFFFFu, i, o);
            if (b2 < b || (b2 == b && i2 < i)) { s = fminf(b, s2); b = b2; i = i2; }
            else                               { s = fminf(s, b2); }
        }
        if (qcol == 0) {
            int row = RM + (t >> 1) * 16 + qrow + (t & 1) * 8;
            bvS[wn * 128 + row] = b;
            svS[wn * 128 + row] = s;
            ivS[wn * 128 + row] = i;
        }
    }
    __syncthreads();

    // final cross-warp-column merge + decision (one thread per point)
    if (tid < 128) {
        float bb = bvS[tid], ss = svS[tid];
        int   ii = ivS[tid];
        #pragma unroll
        for (int w = 1; w < 4; ++w) {
            float b2 = bvS[w * 128 + tid], s2 = svS[w * 128 + tid];
            int   i2 = ivS[w * 128 + tid];
            if (b2 < bb || (b2 == bb && i2 < ii)) { ss = fminf(bb, s2); bb = b2; ii = i2; }
            else                                   { ss = fminf(ss, b2); }
        }
        int n = n0 + tid;
        g_idx[n] = ii;
        int mark = ii;
        if (ss - bb < TAU) {
            int slot = atomicAdd(&g_nref, 1);
            g_rlist[slot] = n;
            mark = -1;                      // tiered refine finalizes later
        } else {
            g_rank[n] = atomicAdd(&g_counts[ii], 1);   // fused rank
        }
        ivS[tid] = mark;
    }
    __syncthreads();

    // stream full one-hot rows (replaces global memset)
    #pragma unroll
    for (int i = 0; i < 32; ++i) {
        int idx = i * 512 + tid;
        int row = idx >> 7, s = idx & 127;
        int m = ivS[row];
        float4 v = make_float4(0.f, 0.f, 0.f, 0.f);
        if ((m >> 2) == s) ((float*)&v)[m & 3] = 1.0f;
        __stcs((float4*)(out + (size_t)(n0 + row) * K_CL + s * 4), v);
    }
}

// ---------------------------------------------------------------------------
// refine1: split-tf32 (3-pass) MMA re-score of near-tie points (79us measured)
// + fused rank for points it finalizes.
// ---------------------------------------------------------------------------
__global__ __launch_bounds__(256)
void refine1_mma(const float* __restrict__ X, const float* __restrict__ C,
                 float* __restrict__ out) {
    const int nref  = g_nref;
    const int tile0 = blockIdx.x * MT2;
    if (tile0 >= nref) return;

    extern __shared__ char smem[];
    const int tid  = threadIdx.x;
    const int wid  = tid >> 5, lane = tid & 31;
    const int qrow = lane >> 2, qcol = lane & 3;
    const int wm   = wid & 1,  wn   = wid >> 1;
    const int RM   = wm * 32,  CN   = wn * 32;

    float* Xh  = (float*)(smem + R_XH);
    float* Xl  = (float*)(smem + R_XL);
    float* Bh[2] = { (float*)(smem + R_BH0), (float*)(smem + R_BH1) };
    float* Bl[2] = { (float*)(smem + R_BL0), (float*)(smem + R_BL1) };
    float* c2s = (float*)(smem + R_C2);
    int*   plist = (int*)(smem + R_PL);
    float* bvS = (float*)(smem + R_BV);
    float* svS = (float*)(smem + R_SV);
    int*   ivS = (int*)  (smem + R_IV);

    c2s[tid]       = g_c2[tid];
    c2s[tid + 256] = g_c2[tid + 256];
    if (tid < MT2) {
        int idx = tile0 + tid;
        plist[tid] = g_rlist[idx < nref ? idx : nref - 1];
    }
    __syncthreads();

    float4 pr[4];
    auto ldgB = [&](int q) {
        const int kt = (q >> 3) * 128, db = (q & 7) * 32;
        #pragma unroll
        for (int i = 0; i < 4; ++i) {
            int idx = i * 256 + tid;
            int r = idx >> 3, s = idx & 7;
            pr[i] = *(const float4*)(C + (size_t)(kt + r) * D_DIM + db + s * 4);
        }
    };
    auto stsB = [&](float* BH, float* BL) {
        #pragma unroll
        for (int i = 0; i < 4; ++i) {
            int idx = i * 256 + tid;
            int r = idx >> 3, s = idx & 7;
            float4 h, l;
            h.x = __uint_as_float(f2tf(pr[i].x)); l.x = __uint_as_float(f2tf(pr[i].x - h.x));
            h.y = __uint_as_float(f2tf(pr[i].y)); l.y = __uint_as_float(f2tf(pr[i].y - h.y));
            h.z = __uint_as_float(f2tf(pr[i].z)); l.z = __uint_as_float(f2tf(pr[i].z - h.z));
            h.w = __uint_as_float(f2tf(pr[i].w)); l.w = __uint_as_float(f2tf(pr[i].w - h.w));
            *(float4*)(BH + r * BSTR2 + s * 4) = h;
            *(float4*)(BL + r * BSTR2 + s * 4) = l;
        }
    };

    ldgB(0);
    #pragma unroll
    for (int i = 0; i < 16; ++i) {
        int idx = i * 256 + tid;
        int r = idx >> 6, s = idx & 63;
        float4 v = *(const float4*)(X + (size_t)plist[r] * D_DIM + s * 4);
        float4 h, l;
        h.x = __uint_as_float(f2tf(v.x)); l.x = __uint_as_float(f2tf(v.x - h.x));
        h.y = __uint_as_float(f2tf(v.y)); l.y = __uint_as_float(f2tf(v.y - h.y));
        h.z = __uint_as_float(f2tf(v.z)); l.z = __uint_as_float(f2tf(v.z - h.z));
        h.w = __uint_as_float(f2tf(v.w)); l.w = __uint_as_float(f2tf(v.w - h.w));
        *(float4*)(Xh + r * 260 + s * 4) = h;
        *(float4*)(Xl + r * 260 + s * 4) = l;
    }
    stsB(Bh[0], Bl[0]);
    ldgB(1);
    __syncthreads();

    float acc[2][4][4];
    #pragma unroll
    for (int a = 0; a < 2; ++a)
        #pragma unroll
        for (int b = 0; b < 4; ++b)
            #pragma unroll
            for (int c = 0; c < 4; ++c) acc[a][b][c] = 0.0f;

    float best[4], sec[4];
    int   idx4[4];
    #pragma unroll
    for (int t = 0; t < 4; ++t) { best[t] = 3.4e38f; sec[t] = 3.4e38f; idx4[t] = 0; }

    for (int q = 0; q < 32; ++q) {
        const int sbuf = q & 1;
        const int dc   = q & 7;
        const float* BsH = Bh[sbuf];
        const float* BsL = Bl[sbuf];

        #pragma unroll
        for (int ks = 0; ks < 4; ++ks) {
            const int dX = dc * 32 + ks * 8 + qcol;
            uint32_t Ah[2][4], Al[2][4];
            #pragma unroll
            for (int mt = 0; mt < 2; ++mt) {
                int r = RM + mt * 16 + qrow;
                Ah[mt][0] = __float_as_uint(Xh[r * 260 + dX]);
                Ah[mt][1] = __float_as_uint(Xh[(r + 8) * 260 + dX]);
                Ah[mt][2] = __float_as_uint(Xh[r * 260 + dX + 4]);
                Ah[mt][3] = __float_as_uint(Xh[(r + 8) * 260 + dX + 4]);
                Al[mt][0] = __float_as_uint(Xl[r * 260 + dX]);
                Al[mt][1] = __float_as_uint(Xl[(r + 8) * 260 + dX]);
                Al[mt][2] = __float_as_uint(Xl[r * 260 + dX + 4]);
                Al[mt][3] = __float_as_uint(Xl[(r + 8) * 260 + dX + 4]);
            }
            uint32_t BhF[4][2], BlF[4][2];
            #pragma unroll
            for (int nt = 0; nt < 4; ++nt) {
                int n = CN + nt * 8 + qrow;
                BhF[nt][0] = __float_as_uint(BsH[n * BSTR2 + ks * 8 + qcol]);
                BhF[nt][1] = __float_as_uint(BsH[n * BSTR2 + ks * 8 + 4 + qcol]);
                BlF[nt][0] = __float_as_uint(BsL[n * BSTR2 + ks * 8 + qcol]);
                BlF[nt][1] = __float_as_uint(BsL[n * BSTR2 + ks * 8 + 4 + qcol]);
            }
            #pragma unroll
            for (int mt = 0; mt < 2; ++mt)
                #pragma unroll
                for (int nt = 0; nt < 4; ++nt) {
                    mma8(acc[mt][nt], Ah[mt], BhF[nt]);
                    mma8(acc[mt][nt], Ah[mt], BlF[nt]);
                    mma8(acc[mt][nt], Al[mt], BhF[nt]);
                }
        }

        if (dc == 7) {
            const int kt = (q >> 3) * 128;
            #pragma unroll
            for (int mt = 0; mt < 2; ++mt) {
                #pragma unroll
                for (int nt = 0; nt < 4; ++nt) {
                    int k0 = kt + CN + nt * 8 + 2 * qcol;
                    float c20 = c2s[k0], c21 = c2s[k0 + 1];
                    float s0 = fmaf(-2.0f, acc[mt][nt][0], c20);
                    float s1 = fmaf(-2.0f, acc[mt][nt][1], c21);
                    float s2 = fmaf(-2.0f, acc[mt][nt][2], c20);
                    float s3 = fmaf(-2.0f, acc[mt][nt][3], c21);
                    int t0 = mt * 2, t1 = mt * 2 + 1;
                    if (s0 < sec[t0]) { if (s0 < best[t0]) { sec[t0] = best[t0]; best[t0] = s0; idx4[t0] = k0; } else sec[t0] = s0; }
                    if (s1 < sec[t0]) { if (s1 < best[t0]) { sec[t0] = best[t0]; best[t0] = s1; idx4[t0] = k0 + 1; } else sec[t0] = s1; }
                    if (s2 < sec[t1]) { if (s2 < best[t1]) { sec[t1] = best[t1]; best[t1] = s2; idx4[t1] = k0; } else sec[t1] = s2; }
                    if (s3 < sec[t1]) { if (s3 < best[t1]) { sec[t1] = best[t1]; best[t1] = s3; idx4[t1] = k0 + 1; } else sec[t1] = s3; }
                    acc[mt][nt][0] = 0.0f; acc[mt][nt][1] = 0.0f;
                    acc[mt][nt][2] = 0.0f; acc[mt][nt][3] = 0.0f;
                }
            }
        }

        __syncthreads();
        if (q + 1 < 32) stsB(Bh[(q + 1) & 1], Bl[(q + 1) & 1]);
        if (q + 2 < 32) ldgB(q + 2);
        if (q + 1 < 32) __syncthreads();
    }

    #pragma unroll
    for (int t = 0; t < 4; ++t) {
        float b = best[t], s = sec[t];
        int   i = idx4[t];
        #pragma unroll
        for (int o = 1; o <= 2; o <<= 1) {
            float b2 = __shfl_xor_sync(0xFFFFFFFFu, b, o);
            float s2 = __shfl_xor_sync(0xFFFFFFFFu, s, o);
            int   i2 = __shfl_xor_sync(0xFFFFFFFFu, i, o);
            if (b2 < b || (b2 == b && i2 < i)) { s = fminf(b, s2); b = b2; i = i2; }
            else                               { s = fminf(s, b2); }
        }
        if (qcol == 0) {
            int row = RM + (t >> 1) * 16 + qrow + (t & 1) * 8;
            bvS[wn * 64 + row] = b;
            svS[wn * 64 + row] = s;
            ivS[wn * 64 + row] = i;
        }
    }
    __syncthreads();

    if (tid < MT2) {
        float bb = bvS[tid], ss = svS[tid];
        int   ii = ivS[tid];
        #pragma unroll
        for (int w = 1; w < 4; ++w) {
            float b2 = bvS[w * 64 + tid], s2 = svS[w * 64 + tid];
            int   i2 = ivS[w * 64 + tid];
            if (b2 < bb || (b2 == bb && i2 < ii)) { ss = fminf(bb, s2); bb = b2; ii = i2; }
            else                                   { ss = fminf(ss, b2); }
        }
        int idx = tile0 + tid;
        if (idx < nref) {
            int n = plist[tid];
            if (ss - bb >= TAU2) {
                g_idx[n] = ii;
                out[(size_t)n * K_CL + ii] = 1.0f;   // row already all-zero
                g_rank[n] = atomicAdd(&g_counts[ii], 1);   // fused rank
            } else {
                int slot = atomicAdd(&g_nref2, 1);
                g_rlist2[slot] = n;                  // exact tier-2 decides
            }
        }
    }
}

// ---------------------------------------------------------------------------
// refine2 (exact tier): Kahan fp32 dots, reference rounding order + fused rank.
// ---------------------------------------------------------------------------
__device__ __forceinline__ void kadd(float& s, float& comp, float t) {
    float y = __fsub_rn(t, comp);
    float u = __fadd_rn(s, y);
    comp = __fsub_rn(__fsub_rn(u, s), y);
    s = u;
}

__global__ __launch_bounds__(256)
void refine2_kernel(const float* __restrict__ X, const float* __restrict__ C,
                    float* __restrict__ out) {
    __shared__ float  xsh[D_DIM];
    __shared__ double xwr[8];
    __shared__ float  x2sh;
    __shared__ float  rv[256];
    __shared__ int    ri[256];

    const int tid  = threadIdx.x;
    const int nref = g_nref2;

    for (int it = blockIdx.x; it < nref; it += gridDim.x) {
        const int n = g_rlist2[it];
        __syncthreads();
        xsh[tid] = X[(size_t)n * D_DIM + tid];
        __syncthreads();
        {
            double p = (double)xsh[tid] * (double)xsh[tid];
            #pragma unroll
            for (int o = 16; o >= 1; o >>= 1)
                p += __shfl_xor_sync(0xFFFFFFFFu, p, o);
            if ((tid & 31) == 0) xwr[tid >> 5] = p;
            __syncthreads();
            if (tid == 0) {
                double t = 0.0;
                #pragma unroll
                for (int w = 0; w < 8; ++w) t += xwr[w];
                x2sh = (float)t;
            }
            __syncthreads();
        }
        const float x2f = x2sh;
        const float4* xs4 = (const float4*)xsh;

        float bv = 3.4e38f;
        int   bi = 0x7fffffff;
        #pragma unroll
        for (int kk = 0; kk < 2; ++kk) {
            const int k = 2 * tid + kk;
            const float4* cp = (const float4*)(C + (size_t)k * D_DIM);
            float s = 0.0f, comp = 0.0f;
            #pragma unroll 4
            for (int j = 0; j < D_DIM / 4; ++j) {
                float4 cv = cp[j];
                float4 xv = xs4[j];
                kadd(s, comp, __fmul_rn(cv.x, xv.x));
                kadd(s, comp, __fmul_rn(cv.y, xv.y));
                kadd(s, comp, __fmul_rn(cv.z, xv.z));
                kadd(s, comp, __fmul_rn(cv.w, xv.w));
            }
            float dotf = __fadd_rn(s, comp);
            float m = __fmul_rn(2.0f, dotf);
            float a = __fsub_rn(x2f, m);
            float dist = __fadd_rn(a, g_c2[k]);
            if (dist < bv || (dist == bv && k < bi)) { bv = dist; bi = k; }
        }
        rv[tid] = bv; ri[tid] = bi;
        __syncthreads();
        #pragma unroll
        for (int st = 128; st > 0; st >>= 1) {
            if (tid < st) {
                float ov = rv[tid + st]; int oi = ri[tid + st];
                if (ov < rv[tid] || (ov == rv[tid] && oi < ri[tid])) {
                    rv[tid] = ov; ri[tid] = oi;
                }
            }
            __syncthreads();
        }
        if (tid == 0) {
            int kwin = ri[0];
            g_idx[n] = kwin;
            out[(size_t)n * K_CL + kwin] = 1.0f;
            g_rank[n] = atomicAdd(&g_counts[kwin], 1);   // fused rank
        }
    }
}

// ---------------------------------------------------------------------------
// sorted-gather accumulation: scan -> scatter -> gather
// ---------------------------------------------------------------------------
__global__ void scan_kernel() {
    __shared__ int s[K_CL];
    int tid = threadIdx.x;
    s[tid] = g_counts[tid];
    __syncthreads();
    #pragma unroll
    for (int off = 1; off < K_CL; off <<= 1) {
        int v = (tid >= off) ? s[tid - off] : 0;
        __syncthreads();
        s[tid] += v;
        __syncthreads();
    }
    g_off[tid] = s[tid] - g_counts[tid];   // exclusive
}

__global__ void scatter_kernel() {
    int n = blockIdx.x * blockDim.x + threadIdx.x;
    if (n >= N_TOT) return;
    g_order[g_off[g_idx[n]] + g_rank[n]] = n;
}

// thread = dim; march PPC sorted points with a register accumulator, atomic
// flush only at cluster boundaries. PPC=128 halves the serial chain vs R16.
__global__ __launch_bounds__(256)
void gather_kernel(const float* __restrict__ X) {
    __shared__ int ord[PPC];
    __shared__ int cls[PPC];
    const int tid = threadIdx.x;
    const int i0  = blockIdx.x * PPC;

    if (tid < PPC) {
        int n = g_order[i0 + tid];
        ord[tid] = n;
        cls[tid] = g_idx[n];
    }
    __syncthreads();

    float a = 0.0f;
    int cur = cls[0];
    #pragma unroll 4
    for (int i = 0; i < PPC; ++i) {
        int c = cls[i];                    // uniform across threads
        if (c != cur) {
            atomicAdd(&g_sums[(size_t)cur * D_DIM + tid], a);
            a = 0.0f;
            cur = c;
        }
        a += X[(size_t)ord[i] * D_DIM + tid];
    }
    atomicAdd(&g_sums[(size_t)cur * D_DIM + tid], a);
}

// ---------------------------------------------------------------------------
__global__ void finalize_kernel(const float* __restrict__ C, float* __restrict__ outc) {
    int t = blockIdx.x * blockDim.x + threadIdx.x;
    if (t >= K_CL * D_DIM) return;
    int k = t >> 8;
    float cnt = (float)g_counts[k];
    float nc  = g_sums[t] / cnt;
    outc[t] = fmaf(0.9f, C[t], 0.1f * nc);
}

// ---------------------------------------------------------------------------
extern "C" void kernel_launch(void* const* d_in, const int* in_sizes, int n_in,
                              void* d_out, int out_size) {
    const float* X = (const float*)d_in[0];
    const float* C = (const float*)d_in[1];
    float* out = (float*)d_out;
    (void)in_sizes; (void)n_in; (void)out_size;

    cudaFuncSetAttribute(argmin_mma, cudaFuncAttributeMaxDynamicSharedMemorySize,
                         SMEM_TOTAL);
    cudaFuncSetAttribute(refine1_mma, cudaFuncAttributeMaxDynamicSharedMemorySize,
                         SMEM2_TOTAL);

    init_kernel<<<(K_CL * D_DIM + 255) / 256, 256>>>(C);
    argmin_mma<<<N_TOT / MT, 512, SMEM_TOTAL>>>(X, C, out);
    refine1_mma<<<N_TOT / MT2, 256, SMEM2_TOTAL>>>(X, C, out);
    refine2_kernel<<<512, 256>>>(X, C, out);
    scan_kernel<<<1, K_CL>>>();
    scatter_kernel<<<N_TOT / 256, 256>>>();
    gather_kernel<<<N_TOT / PPC, 256>>>(X);
    finalize_kernel<<<(K_CL * D_DIM + 255) / 256, 256>>>(C, out + (size_t)N_TOT * K_CL);
}